// round 3
// baseline (speedup 1.0000x reference)
#include <cuda_runtime.h>
#include <cstdint>

// Perception3D: 7-point stencil, 5 output groups per input channel.
// in : [B=4, C=16, D=64, H=64, W=64] fp32
// out: [B=4, C*G=80, D=64, H=64, W=64] fp32, out channel = c*5+g
//   g=0 ident, g=1 6-neighbor sum, g=2 gx, g=3 gy, g=4 gz (zero-padded shifts)
//
// R3: group-split. blockIdx.y = g; each block computes ONE group and writes a
// single sequential stream. Input fits in L2 (67MB < 126MB) and the 5 group
// streams run concurrently, so repeated tap reads are L2 hits. Goal: longer
// pure-write DRAM bursts per plane -> less page thrash / turnaround.

#define Dz 64
#define Hy 64
#define Wx 64
#define PLANE (Dz * Hy * Wx)
#define ROW   Wx
#define SLAB  (Hy * Wx)
#define W4    (Wx / 4)
#define G 5

#define F4Z make_float4(0.f, 0.f, 0.f, 0.f)

__device__ __forceinline__ float4 ld4(const float* p) {
    return *reinterpret_cast<const float4*>(p);
}

__global__ void __launch_bounds__(256)
perception3d_kernel(const float* __restrict__ in, float* __restrict__ out) {
    unsigned tid = blockIdx.x * blockDim.x + threadIdx.x;
    unsigned g   = blockIdx.y;

    unsigned w4 = tid & (W4 - 1);          // 0..15
    unsigned h  = (tid >> 4) & (Hy - 1);   // 0..63
    unsigned d  = (tid >> 10) & (Dz - 1);  // 0..63
    unsigned bc = tid >> 16;               // 0..63

    const float* base = in + (size_t)bc * PLANE + (size_t)d * SLAB + (size_t)h * ROW + (size_t)w4 * 4;

    unsigned b  = bc >> 4;
    unsigned cc = bc & 15;
    size_t spatial = (size_t)d * SLAB + (size_t)h * ROW + (size_t)w4 * 4;
    float* op = out + (size_t)b * (16 * G * PLANE) + (size_t)(cc * G + g) * PLANE + spatial;

    float4 r;

    if (g == 0) {
        // identity
        r = ld4(base);
    } else if (g == 2) {
        // gx = xp - xm (depth +-SLAB)
        float4 xp = (d + 1 < Dz) ? ld4(base + SLAB) : F4Z;
        float4 xm = (d >= 1)     ? ld4(base - SLAB) : F4Z;
        r.x = xp.x - xm.x; r.y = xp.y - xm.y; r.z = xp.z - xm.z; r.w = xp.w - xm.w;
    } else if (g == 3) {
        // gy = yp - ym (height +-ROW)
        float4 yp = (h + 1 < Hy) ? ld4(base + ROW) : F4Z;
        float4 ym = (h >= 1)     ? ld4(base - ROW) : F4Z;
        r.x = yp.x - ym.x; r.y = yp.y - ym.y; r.z = yp.z - ym.z; r.w = yp.w - ym.w;
    } else if (g == 4) {
        // gz = zp - zm (within-row shift)
        float4 c = ld4(base);
        float nextv = (w4 + 1 < W4) ? base[4]  : 0.f;
        float prevv = (w4 >= 1)     ? base[-1] : 0.f;
        float4 zp = make_float4(c.y, c.z, c.w, nextv);
        float4 zm = make_float4(prevv, c.x, c.y, c.z);
        r.x = zp.x - zm.x; r.y = zp.y - zm.y; r.z = zp.z - zm.z; r.w = zp.w - zm.w;
    } else {
        // g == 1: 6-neighbor sum
        float4 c  = ld4(base);
        float4 xp = (d + 1 < Dz) ? ld4(base + SLAB) : F4Z;
        float4 xm = (d >= 1)     ? ld4(base - SLAB) : F4Z;
        float4 yp = (h + 1 < Hy) ? ld4(base + ROW)  : F4Z;
        float4 ym = (h >= 1)     ? ld4(base - ROW)  : F4Z;
        float nextv = (w4 + 1 < W4) ? base[4]  : 0.f;
        float prevv = (w4 >= 1)     ? base[-1] : 0.f;
        float4 zp = make_float4(c.y, c.z, c.w, nextv);
        float4 zm = make_float4(prevv, c.x, c.y, c.z);
        r.x = xp.x + xm.x + yp.x + ym.x + zp.x + zm.x;
        r.y = xp.y + xm.y + yp.y + ym.y + zp.y + zm.y;
        r.z = xp.z + xm.z + yp.z + ym.z + zp.z + zm.z;
        r.w = xp.w + xm.w + yp.w + ym.w + zp.w + zm.w;
    }

    __stcs(reinterpret_cast<float4*>(op), r);
}

extern "C" void kernel_launch(void* const* d_in, const int* in_sizes, int n_in,
                              void* d_out, int out_size) {
    const float* in = (const float*)d_in[0];
    float* out = (float*)d_out;
    // x: 64*64*64*16 / 256 = 16384 blocks over (bc,d,h,w4); y: 5 groups
    dim3 grid(16384, G);
    perception3d_kernel<<<grid, 256>>>(in, out);
}

// round 4
// speedup vs baseline: 1.6776x; 1.6776x over previous
#include <cuda_runtime.h>
#include <cstdint>

// Perception3D: 7-point stencil, 5 output groups per input channel.
// in : [B=4, C=16, D=64, H=64, W=64] fp32
// out: [B=4, C*G=80, D=64, H=64, W=64] fp32, out channel = c*5+g
//   g=0 ident, g=1 6-neighbor sum, g=2 gx, g=3 gy, g=4 gz (zero-padded shifts)
//
// R4: R1 shape (fused, .cs streaming stores) but with 256-bit (v8.f32)
// loads/stores — Blackwell LDG.E.256/STG.E.256. One thread = 8 consecutive
// floats along W. Warp stores 1KB contiguous per plane per instruction.

#define Dz 64
#define Hy 64
#define Wx 64
#define PLANE (Dz * Hy * Wx)
#define ROW   Wx
#define SLAB  (Hy * Wx)
#define W8    (Wx / 8)            // 8 chunks per row
#define G 5

__device__ __forceinline__ void ld8(const float* p, float* v) {
    asm("ld.global.nc.v8.f32 {%0,%1,%2,%3,%4,%5,%6,%7}, [%8];"
        : "=f"(v[0]), "=f"(v[1]), "=f"(v[2]), "=f"(v[3]),
          "=f"(v[4]), "=f"(v[5]), "=f"(v[6]), "=f"(v[7])
        : "l"(p));
}

__device__ __forceinline__ void ld8z(const float* p, float* v, bool ok) {
    if (ok) {
        ld8(p, v);
    } else {
#pragma unroll
        for (int i = 0; i < 8; i++) v[i] = 0.f;
    }
}

__device__ __forceinline__ void st8cs(float* p, const float* v) {
    asm volatile("st.global.cs.v8.f32 [%0], {%1,%2,%3,%4,%5,%6,%7,%8};"
        :: "l"(p),
           "f"(v[0]), "f"(v[1]), "f"(v[2]), "f"(v[3]),
           "f"(v[4]), "f"(v[5]), "f"(v[6]), "f"(v[7])
        : "memory");
}

__global__ void __launch_bounds__(256)
perception3d_kernel(const float* __restrict__ in, float* __restrict__ out) {
    // tid over BC * D * H * W8 = 64*64*64*8 = 2,097,152
    unsigned tid = blockIdx.x * blockDim.x + threadIdx.x;

    unsigned w8 = tid & (W8 - 1);          // 0..7
    unsigned h  = (tid >> 3) & (Hy - 1);   // 0..63
    unsigned d  = (tid >> 9) & (Dz - 1);   // 0..63
    unsigned bc = tid >> 15;               // 0..63

    const float* base = in + (size_t)bc * PLANE + (size_t)d * SLAB + (size_t)h * ROW + (size_t)w8 * 8;

    float c[8], xp[8], xm[8], yp[8], ym[8];
    ld8(base, c);
    ld8z(base + SLAB, xp, d + 1 < Dz);
    ld8z(base - SLAB, xm, d >= 1);
    ld8z(base + ROW,  yp, h + 1 < Hy);
    ld8z(base - ROW,  ym, h >= 1);

    float nextv = (w8 + 1 < W8) ? __ldg(base + 8) : 0.f;
    float prevv = (w8 >= 1)     ? __ldg(base - 1) : 0.f;

    float zp[8], zm[8];
#pragma unroll
    for (int i = 0; i < 8; i++) {
        zp[i] = (i < 7) ? c[i + 1] : nextv;
        zm[i] = (i > 0) ? c[i - 1] : prevv;
    }

    float ns[8], gx[8], gy[8], gz[8];
#pragma unroll
    for (int i = 0; i < 8; i++) {
        ns[i] = xp[i] + xm[i] + yp[i] + ym[i] + zp[i] + zm[i];
        gx[i] = xp[i] - xm[i];
        gy[i] = yp[i] - ym[i];
        gz[i] = zp[i] - zm[i];
    }

    unsigned b  = bc >> 4;
    unsigned cc = bc & 15;
    size_t spatial = (size_t)d * SLAB + (size_t)h * ROW + (size_t)w8 * 8;
    float* ob = out + (size_t)b * (16 * G * PLANE) + (size_t)(cc * G) * PLANE + spatial;

    st8cs(ob,             c);
    st8cs(ob + 1 * PLANE, ns);
    st8cs(ob + 2 * PLANE, gx);
    st8cs(ob + 3 * PLANE, gy);
    st8cs(ob + 4 * PLANE, gz);
}

extern "C" void kernel_launch(void* const* d_in, const int* in_sizes, int n_in,
                              void* d_out, int out_size) {
    const float* in = (const float*)d_in[0];
    float* out = (float*)d_out;
    // 2,097,152 threads / 256 = 8192 blocks
    perception3d_kernel<<<8192, 256>>>(in, out);
}